// round 1
// baseline (speedup 1.0000x reference)
#include <cuda_runtime.h>
#include <cstdint>
#include <cstddef>

// Problem constants (fixed by setup_inputs)
#define NN 4
#define H0 60
#define W0 80
#define H1 60
#define W1 80
#define LL (H0*W0)     // 4800 rows
#define SS (H1*W1)     // 4800 cols
#define THRV 0.2f
#define BR 2

#define TPB 256
#define RPC 32                      // rows per CTA in pass 1
#define NQ (SS/4)                   // 1200 float4 per row
#define KMAX 5                      // ceil(1200/256)

// Scratch (no allocations allowed)
__device__ unsigned g_colmax[NN*SS];     // colmax as u32 bit pattern (nonneg floats)
__device__ float    g_rowmax[NN*LL];
__device__ int      g_rowj[NN*LL];       // min index achieving rowmax
__device__ int      g_rowcnt[NN*LL];     // count of elements == rowmax

__global__ void init_kernel() {
    int i = blockIdx.x * blockDim.x + threadIdx.x;
    if (i < NN*SS) g_colmax[i] = 0u;
}

__device__ __forceinline__ void upd(float v, int j, float& lmax, int& lcnt, int& lidx) {
    if (v > lmax) { lmax = v; lcnt = 1; lidx = j; }
    else if (v == lmax) { lcnt++; }
}

__global__ __launch_bounds__(TPB) void pass1(const float4* __restrict__ conf) {
    const int n    = blockIdx.y;
    const int row0 = blockIdx.x * RPC;
    const int t    = threadIdx.x;
    const int warp = t >> 5, lane = t & 31;

    const float4* base = conf + ((size_t)n * LL + row0) * NQ;

    float4 cmax[KMAX];
#pragma unroll
    for (int k = 0; k < KMAX; k++) cmax[k] = make_float4(0.f, 0.f, 0.f, 0.f);

    __shared__ float s_max[RPC][8];
    __shared__ int   s_cnt[RPC][8];
    __shared__ int   s_idx[RPC][8];

    for (int r = 0; r < RPC; r++) {
        const float4* rowp = base + (size_t)r * NQ;
        float lmax = -1.f; int lcnt = 0; int lidx = 0;
#pragma unroll
        for (int k = 0; k < KMAX; k++) {
            int q = t + k * TPB;           // float4 index within row
            if (q < NQ) {
                float4 v = __ldg(rowp + q);
                cmax[k].x = fmaxf(cmax[k].x, v.x);
                cmax[k].y = fmaxf(cmax[k].y, v.y);
                cmax[k].z = fmaxf(cmax[k].z, v.z);
                cmax[k].w = fmaxf(cmax[k].w, v.w);
                int j = q * 4;
                upd(v.x, j    , lmax, lcnt, lidx);
                upd(v.y, j + 1, lmax, lcnt, lidx);
                upd(v.z, j + 2, lmax, lcnt, lidx);
                upd(v.w, j + 3, lmax, lcnt, lidx);
            }
        }
        // warp-level reduce of (max, cnt, minidx) — no block sync needed
#pragma unroll
        for (int off = 16; off > 0; off >>= 1) {
            float omax = __shfl_down_sync(0xffffffffu, lmax, off);
            int   ocnt = __shfl_down_sync(0xffffffffu, lcnt, off);
            int   oidx = __shfl_down_sync(0xffffffffu, lidx, off);
            if (omax > lmax)       { lmax = omax; lcnt = ocnt; lidx = oidx; }
            else if (omax == lmax) { lcnt += ocnt; lidx = min(lidx, oidx); }
        }
        if (lane == 0) { s_max[r][warp] = lmax; s_cnt[r][warp] = lcnt; s_idx[r][warp] = lidx; }
    }
    __syncthreads();

    // combine 8 warp-partials per row (threads 0..31 -> one row each)
    if (t < RPC) {
        float m = -1.f; int c = 0, ix = 0;
#pragma unroll
        for (int w = 0; w < 8; w++) {
            float om = s_max[t][w];
            if (om > m)       { m = om; c = s_cnt[t][w]; ix = s_idx[t][w]; }
            else if (om == m) { c += s_cnt[t][w]; ix = min(ix, s_idx[t][w]); }
        }
        int gi = n * LL + row0 + t;
        g_rowmax[gi] = m; g_rowj[gi] = ix; g_rowcnt[gi] = c;
    }

    // flush column-max partials
#pragma unroll
    for (int k = 0; k < KMAX; k++) {
        int q = t + k * TPB;
        if (q < NQ) {
            int j = q * 4;
            unsigned* cm = &g_colmax[n * SS + j];
            atomicMax(cm + 0, __float_as_uint(cmax[k].x));
            atomicMax(cm + 1, __float_as_uint(cmax[k].y));
            atomicMax(cm + 2, __float_as_uint(cmax[k].z));
            atomicMax(cm + 3, __float_as_uint(cmax[k].w));
        }
    }
}

__device__ __forceinline__ bool valid1(int j) {
    int r = j / W1, c = j % W1;
    return (r >= BR) & (r < H1 - BR) & (c >= BR) & (c < W1 - BR);
}

// warp per row: resolve candidate / exact tie rescan, write outputs
__global__ __launch_bounds__(256) void pass2(const float* __restrict__ conf,
                                             float* __restrict__ out) {
    int gw = (blockIdx.x * blockDim.x + threadIdx.x) >> 5;
    int lane = threadIdx.x & 31;
    if (gw >= NN * LL) return;
    int n = gw / LL, i = gw % LL;

    float m   = g_rowmax[gw];
    int   cnt = g_rowcnt[gw];
    int   jc  = g_rowj[gw];

    int r0 = i / W0, c0 = i % W0;
    bool v0 = (r0 >= BR) & (r0 < H0 - BR) & (c0 >= BR) & (c0 < W0 - BR);

    float mconf = 0.f; int jid = 0; float mv = 0.f;
    if (v0 && m > THRV) {
        if (cnt == 1) {
            if (valid1(jc) && g_colmax[n * SS + jc] == __float_as_uint(m)) {
                mv = 1.f; jid = jc; mconf = m;
            }
        } else {
            // exact first-True scan over the (rare) tied row
            const float* rowp = conf + (size_t)n * LL * SS + (size_t)i * SS;
            for (int base = 0; base < SS; base += 32) {
                int j = base + lane;
                bool ok = false;
                float v = rowp[j];
                if (v == m) {
                    ok = valid1(j) && (g_colmax[n * SS + j] == __float_as_uint(v));
                }
                unsigned b = __ballot_sync(0xffffffffu, ok);
                if (b) {
                    jid = base + (__ffs(b) - 1);
                    mv = 1.f; mconf = m;
                    break;
                }
            }
        }
    }
    if (lane == 0) {
        out[gw]              = mconf;       // mconf   [N*L]
        out[NN*LL + gw]      = mv;          // mask_v  [N*L]
        out[2*NN*LL + gw]    = (float)jid;  // j_ids   [N*L]
    }
}

extern "C" void kernel_launch(void* const* d_in, const int* in_sizes, int n_in,
                              void* d_out, int out_size) {
    const float* conf = (const float*)d_in[0];
    float* out = (float*)d_out;

    init_kernel<<<(NN*SS + 255)/256, 256>>>();
    dim3 g1(LL / RPC, NN);   // 150 x 4 = 600 CTAs
    pass1<<<g1, TPB>>>((const float4*)conf);
    int warps = NN * LL;     // 19200 warps, warp per row
    pass2<<<(warps * 32 + 255)/256, 256>>>(conf, out);
}